// round 3
// baseline (speedup 1.0000x reference)
#include <cuda_runtime.h>
#include <cuda_bf16.h>

#define N1C 8192
#define N2C 8192
#define BC  2
#define TILE 2048
#define LPQ 8              // lanes per query
#define QPW 4              // queries per warp
#define WARPS 8
#define QPB (WARPS * QPW)  // 32 queries per block

__device__ __forceinline__ bool kvless(float ad, int ai, float bd, int bi) {
    return ad < bd || (ad == bd && ai < bi);
}

// reference-rounding sum of squares: fl(fl(x*x + y*y) + z*z), squares rounded
__device__ __forceinline__ float sqsum_ref(float x, float y, float z) {
    float xx = __fmul_rn(x, x);
    float yy = __fmul_rn(y, y);
    float zz = __fmul_rn(z, z);
    return __fadd_rn(__fadd_rn(xx, yy), zz);
}

__global__ __launch_bounds__(256) void knn_kernel(
    const float* __restrict__ p1, const float* __restrict__ p2,
    const float* __restrict__ c1, float* __restrict__ out)
{
    __shared__ float4 s[TILE];

    const int b    = blockIdx.y;
    const int lane = threadIdx.x & 31;
    const int warp = threadIdx.x >> 5;
    const int sub  = lane >> 3;          // which query within warp (0..3)
    const int l    = lane & (LPQ - 1);   // lane within query group (0..7)
    const int m    = blockIdx.x * QPB + warp * QPW + sub;

    const float* q = p2 + ((size_t)b * N2C + m) * 3;
    const float qx = q[0], qy = q[1], qz = q[2];
    const float sq2 = sqsum_ref(qx, qy, qz);

    float b0 = 3.4e38f, b1 = 3.4e38f, b2 = 3.4e38f;
    int   i0 = 0, i1 = 0, i2 = 0;

    const float* pb = p1 + (size_t)b * N1C * 3;

    for (int t0 = 0; t0 < N1C; t0 += TILE) {
        __syncthreads();
        // cooperative tile load: (x, y, z, ||p||^2 in reference rounding)
        for (int i = threadIdx.x; i < TILE; i += blockDim.x) {
            const float* p = pb + (size_t)(t0 + i) * 3;
            float x = p[0], y = p[1], z = p[2];
            s[i] = make_float4(x, y, z, sqsum_ref(x, y, z));
        }
        __syncthreads();

        #pragma unroll 4
        for (int i = l; i < TILE; i += LPQ) {
            float4 p = s[i];
            // Emulate XLA multiply+reduce (no FMA contraction):
            //   inner = rn(rn(rn(qx*px) + rn(qy*py)) + rn(qz*pz))
            //   d     = rn( rn(sq2+sq1) - 2*inner )   (2*inner exact)
            float m0 = __fmul_rn(qx, p.x);
            float m1 = __fmul_rn(qy, p.y);
            float m2 = __fmul_rn(qz, p.z);
            float inner = __fadd_rn(__fadd_rn(m0, m1), m2);
            float ssum  = __fadd_rn(sq2, p.w);
            float d     = fmaf(-2.0f, inner, ssum);
            if (d < b2) {
                int j = t0 + i;
                if (d < b1) {
                    b2 = b1; i2 = i1;
                    if (d < b0) { b1 = b0; i1 = i0; b0 = d; i0 = j; }
                    else        { b1 = d;  i1 = j; }
                } else { b2 = d; i2 = j; }
            }
        }
    }

    // merge top-3 triples across the 8 lanes of this query group (xor 1,2,4)
    #pragma unroll
    for (int off = 1; off < LPQ; off <<= 1) {
        float o0d = __shfl_xor_sync(0xffffffffu, b0, off);
        int   o0i = __shfl_xor_sync(0xffffffffu, i0, off);
        float o1d = __shfl_xor_sync(0xffffffffu, b1, off);
        int   o1i = __shfl_xor_sync(0xffffffffu, i1, off);
        float o2d = __shfl_xor_sync(0xffffffffu, b2, off);
        int   o2i = __shfl_xor_sync(0xffffffffu, i2, off);

        // truncated odd-even merge of two sorted triples -> smallest 3 of 6
        bool  t0b = kvless(b0, i0, o0d, o0i);
        float m0d = t0b ? b0  : o0d;  int m0i = t0b ? i0  : o0i;
        float M0d = t0b ? o0d : b0;   int M0i = t0b ? o0i : i0;

        bool  t1b = kvless(b1, i1, o1d, o1i);
        float m1d = t1b ? b1  : o1d;  int m1i = t1b ? i1  : o1i;

        bool  t2b = kvless(b2, i2, o2d, o2i);
        float m2d = t2b ? b2  : o2d;  int m2i = t2b ? i2  : o2i;

        bool  t3b = kvless(M0d, M0i, m1d, m1i);
        float r1d = t3b ? M0d : m1d;  int r1i = t3b ? M0i : m1i;
        float x2d = t3b ? m1d : M0d;  int x2i = t3b ? m1i : M0i;

        bool  t4b = kvless(x2d, x2i, m2d, m2i);
        float r2d = t4b ? x2d : m2d;  int r2i = t4b ? x2i : m2i;

        b0 = m0d; i0 = m0i;
        b1 = r1d; i1 = r1i;
        b2 = r2d; i2 = r2i;
    }

    if (l == 0) {
        const float* cb = c1 + (size_t)b * N1C * 3;
        const float* ca = cb + (size_t)i0 * 3;   // rank-0 neighbor
        const float* cc = cb + (size_t)i1 * 3;   // rank-1
        const float* cd = cb + (size_t)i2 * 3;   // rank-2
        float* o = out + ((size_t)b * N2C + m) * 3;
        #pragma unroll
        for (int c = 0; c < 3; c++) {
            // jnp.mean over K: rn(rn(rn(c0+c1)+c2) / 3)
            float ssum = __fadd_rn(__fadd_rn(ca[c], cc[c]), cd[c]);
            o[c] = __fdiv_rn(ssum, 3.0f);
        }
    }
}

extern "C" void kernel_launch(void* const* d_in, const int* in_sizes, int n_in,
                              void* d_out, int out_size) {
    const float* p1 = (const float*)d_in[0];   // points1 [B, N1, 3]
    const float* p2 = (const float*)d_in[1];   // points2 [B, N2, 3]
    const float* c1 = (const float*)d_in[2];   // colors1 [B, N1, 3]
    float* out = (float*)d_out;                // [B, N2, 3] f32

    dim3 grid(N2C / QPB, BC);
    knn_kernel<<<grid, 256>>>(p1, p2, c1, out);
}

// round 4
// speedup vs baseline: 1.1010x; 1.1010x over previous
#include <cuda_runtime.h>
#include <cuda_bf16.h>

#define N1C 8192
#define N2C 8192
#define BC  2
#define TILE 2048
#define LPQ 8              // lanes per query
#define QPW 4              // queries per warp
#define WARPS 8
#define QPB (WARPS * QPW)  // 32 queries per block
#define CHUNK 32           // lane-iterations between threshold refreshes

__device__ __forceinline__ bool kvless(float ad, int ai, float bd, int bi) {
    return ad < bd || (ad == bd && ai < bi);
}

// reference-rounding sum of squares: fl(fl(x*x + y*y) + z*z), squares rounded
__device__ __forceinline__ float sqsum_ref(float x, float y, float z) {
    float xx = __fmul_rn(x, x);
    float yy = __fmul_rn(y, y);
    float zz = __fmul_rn(z, z);
    return __fadd_rn(__fadd_rn(xx, yy), zz);
}

__global__ __launch_bounds__(256) void knn_kernel(
    const float* __restrict__ p1, const float* __restrict__ p2,
    const float* __restrict__ c1, float* __restrict__ out)
{
    __shared__ float4 s[TILE];

    const int b    = blockIdx.y;
    const int lane = threadIdx.x & 31;
    const int warp = threadIdx.x >> 5;
    const int sub  = lane >> 3;          // which query within warp (0..3)
    const int l    = lane & (LPQ - 1);   // lane within query group (0..7)
    const int m    = blockIdx.x * QPB + warp * QPW + sub;

    const float* q = p2 + ((size_t)b * N2C + m) * 3;
    const float qx = q[0], qy = q[1], qz = q[2];
    const float nx = -2.0f * qx, ny = -2.0f * qy, nz = -2.0f * qz; // exact
    const float sq2 = sqsum_ref(qx, qy, qz);

    float b0 = 3.4e38f, b1 = 3.4e38f, b2 = 3.4e38f;
    int   i0 = 0, i1 = 0, i2 = 0;

    const float* pb = p1 + (size_t)b * N1C * 3;

    for (int t0 = 0; t0 < N1C; t0 += TILE) {
        __syncthreads();
        // cooperative tile load: (x, y, z, ||p||^2 in reference rounding)
        for (int i = threadIdx.x; i < TILE; i += blockDim.x) {
            const float* p = pb + (size_t)(t0 + i) * 3;
            float x = p[0], y = p[1], z = p[2];
            s[i] = make_float4(x, y, z, sqsum_ref(x, y, z));
        }
        __syncthreads();

        for (int c = 0; c < TILE / (LPQ * CHUNK); ++c) {
            // refresh filter threshold: group-shared 3rd-best (min over the
            // 8 lanes of this query). Looser-than-true is safe; eps covers
            // fast-path rounding diffs and exact ties.
            float tau = b2;
            tau = fminf(tau, __shfl_xor_sync(0xffffffffu, tau, 1));
            tau = fminf(tau, __shfl_xor_sync(0xffffffffu, tau, 2));
            tau = fminf(tau, __shfl_xor_sync(0xffffffffu, tau, 4));
            const float tauf = __fadd_rn(tau, -sq2) + 1e-3f;

            const float4* sp = s + (c * (LPQ * CHUNK) + l);
            const int jbase = t0 + c * (LPQ * CHUNK) + l;

            #pragma unroll 8
            for (int k = 0; k < CHUNK; ++k) {
                float4 p = sp[k * LPQ];
                // fast approximate distance (contracted FMAs, minus sq2 term)
                float df = fmaf(nz, p.z, fmaf(ny, p.y, fmaf(nx, p.x, p.w)));
                if (df < tauf) {
                    // exact reference-rounded distance:
                    //   inner = rn(rn(rn(qx*px)+rn(qy*py))+rn(qz*pz))
                    //   d     = rn( rn(sq2+sq1) - 2*inner )
                    float m0 = __fmul_rn(qx, p.x);
                    float m1 = __fmul_rn(qy, p.y);
                    float m2 = __fmul_rn(qz, p.z);
                    float inner = __fadd_rn(__fadd_rn(m0, m1), m2);
                    float ssum  = __fadd_rn(sq2, p.w);
                    float d     = fmaf(-2.0f, inner, ssum);
                    if (d < b2) {
                        int j = jbase + k * LPQ;
                        if (d < b1) {
                            b2 = b1; i2 = i1;
                            if (d < b0) { b1 = b0; i1 = i0; b0 = d; i0 = j; }
                            else        { b1 = d;  i1 = j; }
                        } else { b2 = d; i2 = j; }
                    }
                }
            }
        }
    }

    // merge top-3 triples across the 8 lanes of this query group (xor 1,2,4)
    #pragma unroll
    for (int off = 1; off < LPQ; off <<= 1) {
        float o0d = __shfl_xor_sync(0xffffffffu, b0, off);
        int   o0i = __shfl_xor_sync(0xffffffffu, i0, off);
        float o1d = __shfl_xor_sync(0xffffffffu, b1, off);
        int   o1i = __shfl_xor_sync(0xffffffffu, i1, off);
        float o2d = __shfl_xor_sync(0xffffffffu, b2, off);
        int   o2i = __shfl_xor_sync(0xffffffffu, i2, off);

        // truncated odd-even merge of two sorted triples -> smallest 3 of 6
        bool  t0b = kvless(b0, i0, o0d, o0i);
        float m0d = t0b ? b0  : o0d;  int m0i = t0b ? i0  : o0i;
        float M0d = t0b ? o0d : b0;   int M0i = t0b ? o0i : i0;

        bool  t1b = kvless(b1, i1, o1d, o1i);
        float m1d = t1b ? b1  : o1d;  int m1i = t1b ? i1  : o1i;

        bool  t2b = kvless(b2, i2, o2d, o2i);
        float m2d = t2b ? b2  : o2d;  int m2i = t2b ? i2  : o2i;

        bool  t3b = kvless(M0d, M0i, m1d, m1i);
        float r1d = t3b ? M0d : m1d;  int r1i = t3b ? M0i : m1i;
        float x2d = t3b ? m1d : M0d;  int x2i = t3b ? m1i : M0i;

        bool  t4b = kvless(x2d, x2i, m2d, m2i);
        float r2d = t4b ? x2d : m2d;  int r2i = t4b ? x2i : m2i;

        b0 = m0d; i0 = m0i;
        b1 = r1d; i1 = r1i;
        b2 = r2d; i2 = r2i;
    }

    if (l == 0) {
        const float* cb = c1 + (size_t)b * N1C * 3;
        const float* ca = cb + (size_t)i0 * 3;   // rank-0 neighbor
        const float* cc = cb + (size_t)i1 * 3;   // rank-1
        const float* cd = cb + (size_t)i2 * 3;   // rank-2
        float* o = out + ((size_t)b * N2C + m) * 3;
        #pragma unroll
        for (int c = 0; c < 3; c++) {
            // jnp.mean over K: rn(rn(rn(c0+c1)+c2) / 3)
            float ssum = __fadd_rn(__fadd_rn(ca[c], cc[c]), cd[c]);
            o[c] = __fdiv_rn(ssum, 3.0f);
        }
    }
}

extern "C" void kernel_launch(void* const* d_in, const int* in_sizes, int n_in,
                              void* d_out, int out_size) {
    const float* p1 = (const float*)d_in[0];   // points1 [B, N1, 3]
    const float* p2 = (const float*)d_in[1];   // points2 [B, N2, 3]
    const float* c1 = (const float*)d_in[2];   // colors1 [B, N1, 3]
    float* out = (float*)d_out;                // [B, N2, 3] f32

    dim3 grid(N2C / QPB, BC);
    knn_kernel<<<grid, 256>>>(p1, p2, c1, out);
}

// round 5
// speedup vs baseline: 1.1358x; 1.0315x over previous
#include <cuda_runtime.h>
#include <cuda_bf16.h>

#define N1C 8192
#define N2C 8192
#define BC  2
#define TILE 2048
#define LPQ 8              // lanes per query
#define QPW 4              // queries per warp
#define WARPS 8
#define QPB (WARPS * QPW)  // 32 queries per block
#define CHUNK 32           // lane-iterations between threshold refreshes

__device__ __forceinline__ bool kvless(float ad, int ai, float bd, int bi) {
    return ad < bd || (ad == bd && ai < bi);
}

// reference-rounding sum of squares: fl(fl(x*x + y*y) + z*z), squares rounded
__device__ __forceinline__ float sqsum_ref(float x, float y, float z) {
    float xx = __fmul_rn(x, x);
    float yy = __fmul_rn(y, y);
    float zz = __fmul_rn(z, z);
    return __fadd_rn(__fadd_rn(xx, yy), zz);
}

__global__ __launch_bounds__(256) void knn_kernel(
    const float* __restrict__ p1, const float* __restrict__ p2,
    const float* __restrict__ c1, float* __restrict__ out)
{
    __shared__ float4 s[TILE];

    const int b    = blockIdx.y;
    const int lane = threadIdx.x & 31;
    const int warp = threadIdx.x >> 5;
    const int sub  = lane >> 3;          // which query within warp (0..3)
    const int l    = lane & (LPQ - 1);   // lane within query group (0..7)
    const int m    = blockIdx.x * QPB + warp * QPW + sub;

    const float* q = p2 + ((size_t)b * N2C + m) * 3;
    const float qx = q[0], qy = q[1], qz = q[2];
    const float nx = -2.0f * qx, ny = -2.0f * qy, nz = -2.0f * qz; // exact
    const float sq2 = sqsum_ref(qx, qy, qz);

    float b0 = 3.4e38f, b1 = 3.4e38f, b2 = 3.4e38f;
    int   i0 = 0, i1 = 0, i2 = 0;

    const float* pb = p1 + (size_t)b * N1C * 3;

    for (int t0 = 0; t0 < N1C; t0 += TILE) {
        __syncthreads();
        // cooperative tile load: (x, y, z, ||p||^2 in reference rounding)
        for (int i = threadIdx.x; i < TILE; i += blockDim.x) {
            const float* p = pb + (size_t)(t0 + i) * 3;
            float x = p[0], y = p[1], z = p[2];
            s[i] = make_float4(x, y, z, sqsum_ref(x, y, z));
        }
        __syncthreads();

        for (int c = 0; c < TILE / (LPQ * CHUNK); ++c) {
            // ---- refresh filter threshold: EXACT 3rd-smallest of the union
            // of the 8 lanes' top-3 values (values-only odd-even merge).
            // tau >= final-3rd-best at all times -> conservative filter.
            float v0 = b0, v1 = b1, v2 = b2;
            #pragma unroll
            for (int off = 1; off < LPQ; off <<= 1) {
                float o0 = __shfl_xor_sync(0xffffffffu, v0, off);
                float o1 = __shfl_xor_sync(0xffffffffu, v1, off);
                float o2 = __shfl_xor_sync(0xffffffffu, v2, off);
                float M0 = fmaxf(v0, o0);
                float m1 = fminf(v1, o1);
                float m2 = fminf(v2, o2);
                v0 = fminf(v0, o0);
                v1 = fminf(M0, m1);
                v2 = fminf(fmaxf(M0, m1), m2);
            }
            const float tauf = __fadd_rn(v2, -sq2) + 1e-3f;

            const float4* sp = s + (c * (LPQ * CHUNK) + l);
            const int jbase = t0 + c * (LPQ * CHUNK) + l;

            #pragma unroll 8
            for (int k = 0; k < CHUNK; ++k) {
                float4 p = sp[k * LPQ];
                // fast approximate distance (contracted FMAs, minus sq2 term)
                float df = fmaf(nz, p.z, fmaf(ny, p.y, fmaf(nx, p.x, p.w)));
                if (df < tauf) {
                    // exact reference-rounded distance:
                    //   inner = rn(rn(rn(qx*px)+rn(qy*py))+rn(qz*pz))
                    //   d     = rn( rn(sq2+sq1) - 2*inner )
                    float m0 = __fmul_rn(qx, p.x);
                    float m1 = __fmul_rn(qy, p.y);
                    float m2 = __fmul_rn(qz, p.z);
                    float inner = __fadd_rn(__fadd_rn(m0, m1), m2);
                    float ssum  = __fadd_rn(sq2, p.w);
                    float d     = fmaf(-2.0f, inner, ssum);
                    if (d < b2) {
                        int j = jbase + k * LPQ;
                        if (d < b1) {
                            b2 = b1; i2 = i1;
                            if (d < b0) { b1 = b0; i1 = i0; b0 = d; i0 = j; }
                            else        { b1 = d;  i1 = j; }
                        } else { b2 = d; i2 = j; }
                    }
                }
            }
        }
    }

    // merge top-3 triples across the 8 lanes of this query group (xor 1,2,4)
    #pragma unroll
    for (int off = 1; off < LPQ; off <<= 1) {
        float o0d = __shfl_xor_sync(0xffffffffu, b0, off);
        int   o0i = __shfl_xor_sync(0xffffffffu, i0, off);
        float o1d = __shfl_xor_sync(0xffffffffu, b1, off);
        int   o1i = __shfl_xor_sync(0xffffffffu, i1, off);
        float o2d = __shfl_xor_sync(0xffffffffu, b2, off);
        int   o2i = __shfl_xor_sync(0xffffffffu, i2, off);

        // truncated odd-even merge of two sorted triples -> smallest 3 of 6
        bool  t0b = kvless(b0, i0, o0d, o0i);
        float m0d = t0b ? b0  : o0d;  int m0i = t0b ? i0  : o0i;
        float M0d = t0b ? o0d : b0;   int M0i = t0b ? o0i : i0;

        bool  t1b = kvless(b1, i1, o1d, o1i);
        float m1d = t1b ? b1  : o1d;  int m1i = t1b ? i1  : o1i;

        bool  t2b = kvless(b2, i2, o2d, o2i);
        float m2d = t2b ? b2  : o2d;  int m2i = t2b ? i2  : o2i;

        bool  t3b = kvless(M0d, M0i, m1d, m1i);
        float r1d = t3b ? M0d : m1d;  int r1i = t3b ? M0i : m1i;
        float x2d = t3b ? m1d : M0d;  int x2i = t3b ? m1i : M0i;

        bool  t4b = kvless(x2d, x2i, m2d, m2i);
        float r2d = t4b ? x2d : m2d;  int r2i = t4b ? x2i : m2i;

        b0 = m0d; i0 = m0i;
        b1 = r1d; i1 = r1i;
        b2 = r2d; i2 = r2i;
    }

    if (l == 0) {
        const float* cb = c1 + (size_t)b * N1C * 3;
        const float* ca = cb + (size_t)i0 * 3;   // rank-0 neighbor
        const float* cc = cb + (size_t)i1 * 3;   // rank-1
        const float* cd = cb + (size_t)i2 * 3;   // rank-2
        float* o = out + ((size_t)b * N2C + m) * 3;
        #pragma unroll
        for (int c = 0; c < 3; c++) {
            // jnp.mean over K: rn(rn(rn(c0+c1)+c2) / 3)
            float ssum = __fadd_rn(__fadd_rn(ca[c], cc[c]), cd[c]);
            o[c] = __fdiv_rn(ssum, 3.0f);
        }
    }
}

extern "C" void kernel_launch(void* const* d_in, const int* in_sizes, int n_in,
                              void* d_out, int out_size) {
    const float* p1 = (const float*)d_in[0];   // points1 [B, N1, 3]
    const float* p2 = (const float*)d_in[1];   // points2 [B, N2, 3]
    const float* c1 = (const float*)d_in[2];   // colors1 [B, N1, 3]
    float* out = (float*)d_out;                // [B, N2, 3] f32

    dim3 grid(N2C / QPB, BC);
    knn_kernel<<<grid, 256>>>(p1, p2, c1, out);
}